// round 12
// baseline (speedup 1.0000x reference)
#include <cuda_runtime.h>

#define BB 2
#define SS 2048
#define EE 1024
#define HH 16
#define DD 64

typedef unsigned long long u64;
typedef unsigned int u32;

__device__ __forceinline__ u32 cvt_tf32(float f) {
    u32 u; asm("cvt.rna.tf32.f32 %0, %1;" : "=r"(u) : "f"(f)); return u;
}
__device__ __forceinline__ void mma_tf32(float* c, const u32* a, u32 b0, u32 b1) {
    asm("mma.sync.aligned.m16n8k8.row.col.f32.tf32.tf32.f32 "
        "{%0,%1,%2,%3}, {%4,%5,%6,%7}, {%8,%9}, {%0,%1,%2,%3};"
        : "+f"(c[0]), "+f"(c[1]), "+f"(c[2]), "+f"(c[3])
        : "r"(a[0]), "r"(a[1]), "r"(a[2]), "r"(a[3]), "r"(b0), "r"(b1));
}
__device__ __forceinline__ void cp_async16(void* smem, const void* gptr) {
    u32 sa = (u32)__cvta_generic_to_shared(smem);
    asm volatile("cp.async.cg.shared.global [%0], [%1], 16;" :: "r"(sa), "l"(gptr));
}
__device__ __forceinline__ void cp_commit() { asm volatile("cp.async.commit_group;"); }
template<int N> __device__ __forceinline__ void cp_wait() {
    asm volatile("cp.async.wait_group %0;" :: "n"(N));
}

// ---------------- scratch ----------------
__device__ float g_q[BB*HH*SS*DD];     // [b,h,s,d]
__device__ float g_k[BB*HH*SS*DD];
__device__ float g_v[BB*HH*SS*DD];
__device__ float g_attn[BB*SS*EE];     // [b,s,h*d]

// ---------------- QKV projection via tf32 mma, x split hi+lo (R7, validated) ----------------
#define QSTR 36
__global__ __launch_bounds__(256) void qkv_kernel(
    const float* __restrict__ x,
    const float* __restrict__ Wq, const float* __restrict__ Bq,
    const float* __restrict__ Wk, const float* __restrict__ Bk,
    const float* __restrict__ Wv, const float* __restrict__ Bv)
{
    __shared__ u32 Ah[64*QSTR];
    __shared__ u32 Al[64*QSTR];
    __shared__ u32 Wsm[192*QSTR];

    int tid  = threadIdx.x;
    int warp = tid >> 5;
    int lane = tid & 31;
    int g    = lane >> 2;
    int tg   = lane & 3;
    int wm0  = (warp >> 2) * 32;
    int wn0  = (warp & 3) * 48;
    int r0   = blockIdx.x * 64;

    const float* Ws[3] = {Wq, Wk, Wv};

    float acc[2][6][4];
    #pragma unroll
    for (int mf = 0; mf < 2; ++mf)
        #pragma unroll
        for (int nf = 0; nf < 6; ++nf)
            #pragma unroll
            for (int j = 0; j < 4; ++j) acc[mf][nf][j] = 0.f;

    for (int k0 = 0; k0 < 64; k0 += 32) {
        if (k0) __syncthreads();
        #pragma unroll
        for (int it = 0; it < 2; ++it) {
            int idx = it*256 + tid;
            int row = idx >> 3;
            int c4  = (idx & 7) * 4;
            float4 v = *(const float4*)(x + (size_t)(r0+row)*64 + k0 + c4);
            uint4 h, l;
            h.x = cvt_tf32(v.x); l.x = cvt_tf32(v.x - __uint_as_float(h.x));
            h.y = cvt_tf32(v.y); l.y = cvt_tf32(v.y - __uint_as_float(h.y));
            h.z = cvt_tf32(v.z); l.z = cvt_tf32(v.z - __uint_as_float(h.z));
            h.w = cvt_tf32(v.w); l.w = cvt_tf32(v.w - __uint_as_float(h.w));
            *(uint4*)&Ah[row*QSTR + c4] = h;
            *(uint4*)&Al[row*QSTR + c4] = l;
        }
        #pragma unroll
        for (int it = 0; it < 6; ++it) {
            int idx = it*256 + tid;
            int row = idx >> 3;
            int c4  = (idx & 7) * 4;
            float4 v = *(const float4*)(Ws[row >> 6] + (size_t)(row & 63)*64 + k0 + c4);
            uint4 h;
            h.x = cvt_tf32(v.x); h.y = cvt_tf32(v.y);
            h.z = cvt_tf32(v.z); h.w = cvt_tf32(v.w);
            *(uint4*)&Wsm[row*QSTR + c4] = h;
        }
        __syncthreads();

        #pragma unroll
        for (int ks = 0; ks < 4; ++ks) {
            int kk = ks * 8;
            u32 ah[2][4], al[2][4];
            #pragma unroll
            for (int mf = 0; mf < 2; ++mf) {
                int mr = wm0 + mf*16;
                ah[mf][0] = Ah[(mr+g)*QSTR   + kk + tg];
                ah[mf][1] = Ah[(mr+g+8)*QSTR + kk + tg];
                ah[mf][2] = Ah[(mr+g)*QSTR   + kk + tg + 4];
                ah[mf][3] = Ah[(mr+g+8)*QSTR + kk + tg + 4];
                al[mf][0] = Al[(mr+g)*QSTR   + kk + tg];
                al[mf][1] = Al[(mr+g+8)*QSTR + kk + tg];
                al[mf][2] = Al[(mr+g)*QSTR   + kk + tg + 4];
                al[mf][3] = Al[(mr+g+8)*QSTR + kk + tg + 4];
            }
            #pragma unroll
            for (int nf = 0; nf < 6; ++nf) {
                u32 b0 = Wsm[(wn0 + nf*8 + g)*QSTR + kk + tg];
                u32 b1 = Wsm[(wn0 + nf*8 + g)*QSTR + kk + tg + 4];
                #pragma unroll
                for (int mf = 0; mf < 2; ++mf) {
                    mma_tf32(acc[mf][nf], ah[mf], b0, b1);
                    mma_tf32(acc[mf][nf], al[mf], b0, b1);
                }
            }
        }
    }

    const float* Bias[3] = {Bq, Bk, Bv};
    float* Gs[3];
    Gs[0] = g_q; Gs[1] = g_k; Gs[2] = g_v;
    #pragma unroll
    for (int mf = 0; mf < 2; ++mf) {
        int ra = r0 + wm0 + mf*16 + g;
        int rb = ra + 8;
        #pragma unroll
        for (int nf = 0; nf < 6; ++nf) {
            int gc  = wn0 + nf*8 + 2*tg;
            int mat = gc >> 6;
            int c   = gc & 63;
            float b0 = Bias[mat][c], b1 = Bias[mat][c+1];
            {
                int h = ra & 15, bs = ra >> 4, s = bs & 2047, b = bs >> 11;
                float2 t; t.x = acc[mf][nf][0] + b0; t.y = acc[mf][nf][1] + b1;
                *(float2*)(Gs[mat] + ((size_t)((b*HH + h)*SS) + s)*DD + c) = t;
            }
            {
                int h = rb & 15, bs = rb >> 4, s = bs & 2047, b = bs >> 11;
                float2 t; t.x = acc[mf][nf][2] + b0; t.y = acc[mf][nf][3] + b1;
                *(float2*)(Gs[mat] + ((size_t)((b*HH + h)*SS) + s)*DD + c) = t;
            }
        }
    }
}

// ---------------- flash attention: 128-row q-tile, 8 warps, cp.async pipelined ----------------
#define KSTR 68
// Kt + Vt + Pex (each 64*68 u32) + staging stK/stV (each 64*64 f32) = 84992 B
#define ATTN_SMEM ((3*64*KSTR + 2*64*64)*4)

__device__ __forceinline__ void attn_issue_tile(
    const float* Kb, const float* Vb, float* stK, float* stV, int k0, int tid)
{
    #pragma unroll
    for (int u = 0; u < 4; ++u) {
        int lin = u*256 + tid;
        int key = lin >> 4;
        int d4  = (lin & 15) * 4;
        cp_async16(stK + key*64 + d4, Kb + (size_t)(k0+key)*64 + d4);
        cp_async16(stV + key*64 + d4, Vb + (size_t)(k0+key)*64 + d4);
    }
}

__global__ void __launch_bounds__(256, 2) attn_kernel()
{
    extern __shared__ u32 dsm[];
    u32* Kt  = dsm;
    u32* Vt  = Kt + 64*KSTR;
    u32* Pex = Vt + 64*KSTR;
    float* stK = (float*)(Pex + 64*KSTR);
    float* stV = stK + 64*64;

    int tid  = threadIdx.x;
    int warp = tid >> 5;
    int lane = tid & 31;
    int g    = lane >> 2;
    int tg   = lane & 3;

    int bh = blockIdx.y;
    int qt = 15 - (int)blockIdx.x;        // heavy blocks first
    int q0 = qt * 128;
    int ntiles = 2*qt + 2;

    const float* Qb = g_q + (size_t)bh*SS*DD;
    const float* Kb = g_k + (size_t)bh*SS*DD;
    const float* Vb = g_v + (size_t)bh*SS*DD;

    int base = q0 + warp*16;              // this warp's 16 rows: base..base+15
    int r0 = base + g;
    int r1 = r0 + 8;

    // prefetch tile 0
    attn_issue_tile(Kb, Vb, stK, stV, 0, tid);
    cp_commit();

    u32 qa[8][4];
    #pragma unroll
    for (int k = 0; k < 8; ++k) {
        qa[k][0] = cvt_tf32(Qb[(size_t)r0*64 + k*8 + tg]     * 0.125f);
        qa[k][1] = cvt_tf32(Qb[(size_t)r1*64 + k*8 + tg]     * 0.125f);
        qa[k][2] = cvt_tf32(Qb[(size_t)r0*64 + k*8 + tg + 4] * 0.125f);
        qa[k][3] = cvt_tf32(Qb[(size_t)r1*64 + k*8 + tg + 4] * 0.125f);
    }

    float accO[8][4];
    #pragma unroll
    for (int n = 0; n < 8; ++n)
        #pragma unroll
        for (int j = 0; j < 4; ++j) accO[n][j] = 0.f;
    float m0 = -3.0e38f, m1 = -3.0e38f, l0 = 0.f, l1 = 0.f;

    u32* Pw = (warp < 4) ? (Kt + warp*16*KSTR) : (Pex + (warp-4)*16*KSTR);

    for (int t = 0; t < ntiles; ++t) {
        int k0 = t * 64;
        cp_wait<0>();
        __syncthreads();                 // staging ready; Kt/Vt free (prev compute done)

        // producer: raw fp32 -> tf32 operands
        #pragma unroll
        for (int u = 0; u < 4; ++u) {
            int lin = u*256 + tid;
            int key = lin >> 4;
            int d4  = (lin & 15) * 4;
            float4 kv = *(const float4*)(stK + key*64 + d4);
            float4 vv = *(const float4*)(stV + key*64 + d4);
            uint4 ku, vu;
            ku.x = cvt_tf32(kv.x); ku.y = cvt_tf32(kv.y); ku.z = cvt_tf32(kv.z); ku.w = cvt_tf32(kv.w);
            vu.x = cvt_tf32(vv.x); vu.y = cvt_tf32(vv.y); vu.z = cvt_tf32(vv.z); vu.w = cvt_tf32(vv.w);
            *(uint4*)&Kt[key*KSTR + d4] = ku;
            *(uint4*)&Vt[key*KSTR + d4] = vu;
        }
        __syncthreads();                 // operands ready; staging free

        if (t + 1 < ntiles) attn_issue_tile(Kb, Vb, stK, stV, k0 + 64, tid);
        cp_commit();

        bool active = (k0 <= base + 15); // warp-uniform: any unmasked col for this warp
        float sfr[8][4];
        if (active) {
            // S = Q K^T
            #pragma unroll
            for (int n = 0; n < 8; ++n) {
                float c[4] = {0.f, 0.f, 0.f, 0.f};
                #pragma unroll
                for (int k = 0; k < 8; ++k) {
                    u32 b0 = Kt[(n*8 + g)*KSTR + k*8 + tg];
                    u32 b1 = Kt[(n*8 + g)*KSTR + k*8 + tg + 4];
                    mma_tf32(c, qa[k], b0, b1);
                }
                sfr[n][0] = c[0]; sfr[n][1] = c[1]; sfr[n][2] = c[2]; sfr[n][3] = c[3];
            }

            if (k0 + 63 > base) {        // diagonal region for this warp
                #pragma unroll
                for (int n = 0; n < 8; ++n) {
                    int col = k0 + n*8 + 2*tg;
                    if (col     > r0) sfr[n][0] = -1e30f;
                    if (col + 1 > r0) sfr[n][1] = -1e30f;
                    if (col     > r1) sfr[n][2] = -1e30f;
                    if (col + 1 > r1) sfr[n][3] = -1e30f;
                }
            }

            float mx0 = -3.0e38f, mx1 = -3.0e38f;
            #pragma unroll
            for (int n = 0; n < 8; ++n) {
                mx0 = fmaxf(mx0, fmaxf(sfr[n][0], sfr[n][1]));
                mx1 = fmaxf(mx1, fmaxf(sfr[n][2], sfr[n][3]));
            }
            mx0 = fmaxf(mx0, __shfl_xor_sync(0xffffffffu, mx0, 1));
            mx0 = fmaxf(mx0, __shfl_xor_sync(0xffffffffu, mx0, 2));
            mx1 = fmaxf(mx1, __shfl_xor_sync(0xffffffffu, mx1, 1));
            mx1 = fmaxf(mx1, __shfl_xor_sync(0xffffffffu, mx1, 2));
            float nm0 = fmaxf(m0, mx0), nm1 = fmaxf(m1, mx1);
            float cr0 = __expf(m0 - nm0), cr1 = __expf(m1 - nm1);
            m0 = nm0; m1 = nm1;
            l0 *= cr0; l1 *= cr1;
            #pragma unroll
            for (int n = 0; n < 8; ++n) {
                accO[n][0] *= cr0; accO[n][1] *= cr0;
                accO[n][2] *= cr1; accO[n][3] *= cr1;
            }
            float ps0 = 0.f, ps1 = 0.f;
            #pragma unroll
            for (int n = 0; n < 8; ++n) {   // p overwrites sfr in place
                sfr[n][0] = __expf(sfr[n][0] - nm0);
                sfr[n][1] = __expf(sfr[n][1] - nm0);
                sfr[n][2] = __expf(sfr[n][2] - nm1);
                sfr[n][3] = __expf(sfr[n][3] - nm1);
                ps0 += sfr[n][0] + sfr[n][1];
                ps1 += sfr[n][2] + sfr[n][3];
            }
            l0 += ps0; l1 += ps1;
        }

        __syncthreads();                 // all warps done reading Kt (QK)
        if (active) {
            #pragma unroll
            for (int n = 0; n < 8; ++n) {
                Pw[g*KSTR       + n*8 + 2*tg]     = cvt_tf32(sfr[n][0]);
                Pw[g*KSTR       + n*8 + 2*tg + 1] = cvt_tf32(sfr[n][1]);
                Pw[(g+8)*KSTR   + n*8 + 2*tg]     = cvt_tf32(sfr[n][2]);
                Pw[(g+8)*KSTR   + n*8 + 2*tg + 1] = cvt_tf32(sfr[n][3]);
            }
            __syncwarp();

            #pragma unroll
            for (int k2 = 0; k2 < 8; ++k2) {
                u32 a[4];
                a[0] = Pw[g*KSTR     + k2*8 + tg];
                a[1] = Pw[(g+8)*KSTR + k2*8 + tg];
                a[2] = Pw[g*KSTR     + k2*8 + tg + 4];
                a[3] = Pw[(g+8)*KSTR + k2*8 + tg + 4];
                #pragma unroll
                for (int n2 = 0; n2 < 8; ++n2) {
                    u32 b0 = Vt[(k2*8 + tg)*KSTR     + n2*8 + g];
                    u32 b1 = Vt[(k2*8 + tg + 4)*KSTR + n2*8 + g];
                    mma_tf32(accO[n2], a, b0, b1);
                }
            }
        }
    }

    l0 += __shfl_xor_sync(0xffffffffu, l0, 1);
    l0 += __shfl_xor_sync(0xffffffffu, l0, 2);
    l1 += __shfl_xor_sync(0xffffffffu, l1, 1);
    l1 += __shfl_xor_sync(0xffffffffu, l1, 2);
    float inv0 = 1.f / l0, inv1 = 1.f / l1;

    int b = bh >> 4, h = bh & (HH-1);
    float* out0 = g_attn + ((size_t)(b*SS + r0))*EE + h*DD;
    float* out1 = g_attn + ((size_t)(b*SS + r1))*EE + h*DD;
    #pragma unroll
    for (int n2 = 0; n2 < 8; ++n2) {
        float2 v0, v1;
        v0.x = accO[n2][0]*inv0; v0.y = accO[n2][1]*inv0;
        v1.x = accO[n2][2]*inv1; v1.y = accO[n2][3]*inv1;
        *(float2*)(out0 + n2*8 + 2*tg) = v0;
        *(float2*)(out1 + n2*8 + 2*tg) = v1;
    }
}

// ---------------- output projection: tf32 mma + cp.async 2-stage, BK=32 (R11, validated) ----------------
#define PK 32
#define PSTR2 36
#define PROJ_SMEM (2*128*PSTR2*4 + 2*2*128*PK*4)

__device__ __forceinline__ void proj_issue(
    const float* __restrict__ W, float* stA, float* stB,
    int m0, int n0, int i, int tid)
{
    if (i < EE/PK) {
        int k0 = i * PK;
        float* sA = stA + (i & 1) * 128*PK;
        float* sB = stB + (i & 1) * 128*PK;
        #pragma unroll
        for (int it = 0; it < 4; ++it) {
            int idx = it*256 + tid;
            int row = idx >> 3;
            int c4  = (idx & 7) * 4;
            cp_async16(sA + row*PK + c4, g_attn + (size_t)(m0+row)*EE + k0 + c4);
            cp_async16(sB + row*PK + c4, W + (size_t)(n0+row)*EE + k0 + c4);
        }
    }
    cp_commit();
}

__global__ __launch_bounds__(256) void proj_kernel(
    const float* __restrict__ W, const float* __restrict__ bias, float* __restrict__ out)
{
    extern __shared__ u32 dsm[];
    u32* As = dsm;
    u32* Bs = dsm + 128*PSTR2;
    float* stA = (float*)(dsm + 2*128*PSTR2);
    float* stB = stA + 2*128*PK;

    int tid  = threadIdx.x;
    int warp = tid >> 5;
    int lane = tid & 31;
    int g    = lane >> 2;
    int tg   = lane & 3;
    int wm0  = (warp >> 1) * 32;
    int wn0  = (warp & 1) * 64;
    int m0   = blockIdx.y * 128;
    int n0   = blockIdx.x * 128;

    float acc[2][8][4];
    #pragma unroll
    for (int mf = 0; mf < 2; ++mf)
        #pragma unroll
        for (int nf = 0; nf < 8; ++nf)
            #pragma unroll
            for (int j = 0; j < 4; ++j) acc[mf][nf][j] = 0.f;

    proj_issue(W, stA, stB, m0, n0, 0, tid);
    proj_issue(W, stA, stB, m0, n0, 1, tid);

    for (int i = 0; i < EE/PK; ++i) {
        cp_wait<1>();
        __syncthreads();

        float* sA = stA + (i & 1) * 128*PK;
        float* sB = stB + (i & 1) * 128*PK;
        #pragma unroll
        for (int it = 0; it < 4; ++it) {
            int idx = it*256 + tid;
            int row = idx >> 3;
            int c4  = (idx & 7) * 4;
            float4 a = *(const float4*)(sA + row*PK + c4);
            uint4 ha;
            ha.x = cvt_tf32(a.x); ha.y = cvt_tf32(a.y); ha.z = cvt_tf32(a.z); ha.w = cvt_tf32(a.w);
            *(uint4*)&As[row*PSTR2 + c4] = ha;
            float4 b = *(const float4*)(sB + row*PK + c4);
            uint4 hb;
            hb.x = cvt_tf32(b.x); hb.y = cvt_tf32(b.y); hb.z = cvt_tf32(b.z); hb.w = cvt_tf32(b.w);
            *(uint4*)&Bs[row*PSTR2 + c4] = hb;
        }
        __syncthreads();

        proj_issue(W, stA, stB, m0, n0, i + 2, tid);

        #pragma unroll
        for (int ks = 0; ks < 4; ++ks) {
            int kk = ks * 8;
            u32 a[2][4];
            #pragma unroll
            for (int mf = 0; mf < 2; ++mf) {
                int mr = wm0 + mf*16;
                a[mf][0] = As[(mr+g)*PSTR2   + kk + tg];
                a[mf][1] = As[(mr+g+8)*PSTR2 + kk + tg];
                a[mf][2] = As[(mr+g)*PSTR2   + kk + tg + 4];
                a[mf][3] = As[(mr+g+8)*PSTR2 + kk + tg + 4];
            }
            #pragma unroll
            for (int nf = 0; nf < 8; ++nf) {
                u32 b0 = Bs[(wn0 + nf*8 + g)*PSTR2 + kk + tg];
                u32 b1 = Bs[(wn0 + nf*8 + g)*PSTR2 + kk + tg + 4];
                #pragma unroll
                for (int mf = 0; mf < 2; ++mf)
                    mma_tf32(acc[mf][nf], a[mf], b0, b1);
            }
        }
    }

    #pragma unroll
    for (int mf = 0; mf < 2; ++mf) {
        int ra = m0 + wm0 + mf*16 + g;
        int rb = ra + 8;
        #pragma unroll
        for (int nf = 0; nf < 8; ++nf) {
            int gc = n0 + wn0 + nf*8 + 2*tg;
            float b0 = bias[gc], b1 = bias[gc+1];
            float2 t0, t1;
            t0.x = acc[mf][nf][0] + b0; t0.y = acc[mf][nf][1] + b1;
            t1.x = acc[mf][nf][2] + b0; t1.y = acc[mf][nf][3] + b1;
            *(float2*)(out + (size_t)ra*EE + gc) = t0;
            *(float2*)(out + (size_t)rb*EE + gc) = t1;
        }
    }
}

// ---------------- launch ----------------
extern "C" void kernel_launch(void* const* d_in, const int* in_sizes, int n_in,
                              void* d_out, int out_size) {
    const float* x  = (const float*)d_in[0];
    const float* Wq = (const float*)d_in[1];
    const float* Bq = (const float*)d_in[2];
    const float* Wk = (const float*)d_in[3];
    const float* Bk = (const float*)d_in[4];
    const float* Wv = (const float*)d_in[5];
    const float* Bv = (const float*)d_in[6];
    const float* Pw = (const float*)d_in[7];
    const float* Pb = (const float*)d_in[8];
    float* out = (float*)d_out;

    cudaFuncSetAttribute(attn_kernel, cudaFuncAttributeMaxDynamicSharedMemorySize, ATTN_SMEM);
    cudaFuncSetAttribute(proj_kernel, cudaFuncAttributeMaxDynamicSharedMemorySize, PROJ_SMEM);

    qkv_kernel<<<1024, 256>>>(x, Wq, Bq, Wk, Bk, Wv, Bv);
    attn_kernel<<<dim3(16, 32), 256, ATTN_SMEM>>>();
    proj_kernel<<<dim3(8, 32), 256, PROJ_SMEM>>>(Pw, Pb, out);
}

// round 16
// speedup vs baseline: 1.1380x; 1.1380x over previous
#include <cuda_runtime.h>

#define BB 2
#define SS 2048
#define EE 1024
#define HH 16
#define DD 64

typedef unsigned long long u64;
typedef unsigned int u32;

__device__ __forceinline__ u32 cvt_tf32(float f) {
    u32 u; asm("cvt.rna.tf32.f32 %0, %1;" : "=r"(u) : "f"(f)); return u;
}
__device__ __forceinline__ void mma_tf32(float* c, const u32* a, u32 b0, u32 b1) {
    asm("mma.sync.aligned.m16n8k8.row.col.f32.tf32.tf32.f32 "
        "{%0,%1,%2,%3}, {%4,%5,%6,%7}, {%8,%9}, {%0,%1,%2,%3};"
        : "+f"(c[0]), "+f"(c[1]), "+f"(c[2]), "+f"(c[3])
        : "r"(a[0]), "r"(a[1]), "r"(a[2]), "r"(a[3]), "r"(b0), "r"(b1));
}
__device__ __forceinline__ void cp_async16(void* smem, const void* gptr) {
    u32 sa = (u32)__cvta_generic_to_shared(smem);
    asm volatile("cp.async.cg.shared.global [%0], [%1], 16;" :: "r"(sa), "l"(gptr));
}
__device__ __forceinline__ void cp_commit() { asm volatile("cp.async.commit_group;"); }
template<int N> __device__ __forceinline__ void cp_wait() {
    asm volatile("cp.async.wait_group %0;" :: "n"(N));
}

// ---------------- scratch ----------------
__device__ float g_q[BB*HH*SS*DD];     // [b,h,s,d]
__device__ float g_k[BB*HH*SS*DD];
__device__ float g_v[BB*HH*SS*DD];
__device__ float g_attn[BB*SS*EE];     // [b,s,h*d]

// ---------------- QKV projection via tf32 mma, x split hi+lo (validated) ----------------
#define QSTR 36
__global__ __launch_bounds__(256) void qkv_kernel(
    const float* __restrict__ x,
    const float* __restrict__ Wq, const float* __restrict__ Bq,
    const float* __restrict__ Wk, const float* __restrict__ Bk,
    const float* __restrict__ Wv, const float* __restrict__ Bv)
{
    __shared__ u32 Ah[64*QSTR];
    __shared__ u32 Al[64*QSTR];
    __shared__ u32 Wsm[192*QSTR];

    int tid  = threadIdx.x;
    int warp = tid >> 5;
    int lane = tid & 31;
    int g    = lane >> 2;
    int tg   = lane & 3;
    int wm0  = (warp >> 2) * 32;
    int wn0  = (warp & 3) * 48;
    int r0   = blockIdx.x * 64;

    const float* Ws[3] = {Wq, Wk, Wv};

    float acc[2][6][4];
    #pragma unroll
    for (int mf = 0; mf < 2; ++mf)
        #pragma unroll
        for (int nf = 0; nf < 6; ++nf)
            #pragma unroll
            for (int j = 0; j < 4; ++j) acc[mf][nf][j] = 0.f;

    int lr = tid >> 2;
    int lk = (tid & 3) * 4;

    for (int k0 = 0; k0 < 64; k0 += 32) {
        if (k0) __syncthreads();
        #pragma unroll
        for (int it = 0; it < 2; ++it) {
            int idx = it*256 + tid;
            int row = idx >> 3;
            int c4  = (idx & 7) * 4;
            float4 v = *(const float4*)(x + (size_t)(r0+row)*64 + k0 + c4);
            uint4 h, l;
            h.x = cvt_tf32(v.x); l.x = cvt_tf32(v.x - __uint_as_float(h.x));
            h.y = cvt_tf32(v.y); l.y = cvt_tf32(v.y - __uint_as_float(h.y));
            h.z = cvt_tf32(v.z); l.z = cvt_tf32(v.z - __uint_as_float(h.z));
            h.w = cvt_tf32(v.w); l.w = cvt_tf32(v.w - __uint_as_float(h.w));
            *(uint4*)&Ah[row*QSTR + c4] = h;
            *(uint4*)&Al[row*QSTR + c4] = l;
        }
        #pragma unroll
        for (int it = 0; it < 6; ++it) {
            int idx = it*256 + tid;
            int row = idx >> 3;
            int c4  = (idx & 7) * 4;
            float4 v = *(const float4*)(Ws[row >> 6] + (size_t)(row & 63)*64 + k0 + c4);
            uint4 h;
            h.x = cvt_tf32(v.x); h.y = cvt_tf32(v.y);
            h.z = cvt_tf32(v.z); h.w = cvt_tf32(v.w);
            *(uint4*)&Wsm[row*QSTR + c4] = h;
        }
        __syncthreads();

        #pragma unroll
        for (int ks = 0; ks < 4; ++ks) {
            int kk = ks * 8;
            u32 ah[2][4], al[2][4];
            #pragma unroll
            for (int mf = 0; mf < 2; ++mf) {
                int mr = wm0 + mf*16;
                ah[mf][0] = Ah[(mr+g)*QSTR   + kk + tg];
                ah[mf][1] = Ah[(mr+g+8)*QSTR + kk + tg];
                ah[mf][2] = Ah[(mr+g)*QSTR   + kk + tg + 4];
                ah[mf][3] = Ah[(mr+g+8)*QSTR + kk + tg + 4];
                al[mf][0] = Al[(mr+g)*QSTR   + kk + tg];
                al[mf][1] = Al[(mr+g+8)*QSTR + kk + tg];
                al[mf][2] = Al[(mr+g)*QSTR   + kk + tg + 4];
                al[mf][3] = Al[(mr+g+8)*QSTR + kk + tg + 4];
            }
            #pragma unroll
            for (int nf = 0; nf < 6; ++nf) {
                u32 b0 = Wsm[(wn0 + nf*8 + g)*QSTR + kk + tg];
                u32 b1 = Wsm[(wn0 + nf*8 + g)*QSTR + kk + tg + 4];
                #pragma unroll
                for (int mf = 0; mf < 2; ++mf) {
                    mma_tf32(acc[mf][nf], ah[mf], b0, b1);
                    mma_tf32(acc[mf][nf], al[mf], b0, b1);
                }
            }
        }
    }

    const float* Bias[3] = {Bq, Bk, Bv};
    float* Gs[3];
    Gs[0] = g_q; Gs[1] = g_k; Gs[2] = g_v;
    #pragma unroll
    for (int mf = 0; mf < 2; ++mf) {
        int ra = r0 + wm0 + mf*16 + g;
        int rb = ra + 8;
        #pragma unroll
        for (int nf = 0; nf < 6; ++nf) {
            int gc  = wn0 + nf*8 + 2*tg;
            int mat = gc >> 6;
            int c   = gc & 63;
            float b0 = Bias[mat][c], b1 = Bias[mat][c+1];
            {
                int h = ra & 15, bs = ra >> 4, s = bs & 2047, b = bs >> 11;
                float2 t; t.x = acc[mf][nf][0] + b0; t.y = acc[mf][nf][1] + b1;
                *(float2*)(Gs[mat] + ((size_t)((b*HH + h)*SS) + s)*DD + c) = t;
            }
            {
                int h = rb & 15, bs = rb >> 4, s = bs & 2047, b = bs >> 11;
                float2 t; t.x = acc[mf][nf][2] + b0; t.y = acc[mf][nf][3] + b1;
                *(float2*)(Gs[mat] + ((size_t)((b*HH + h)*SS) + s)*DD + c) = t;
            }
        }
    }
}

// ---------------- flash attention: tf32 mma, fragment-order K/V (LDS.128 B-frags) ----------------
// Kf blocks: (n*4+kp), 140 u32 stride, lane*4 + ko*2 + h
// Vf blocks: (k2p*8+n2), 140 u32 stride, lane*4 + k2o*2 + h
#define FBLK 140
#define PSTRA 68
#define ATTN_SMEM ((2*32*FBLK + 2*64*64)*4)   // Kf+Vf 35840B + staging 32768B = 68608B

__device__ __forceinline__ void attn_issue_tile(
    const float* Kb, const float* Vb, float* stK, float* stV, int k0, int tid)
{
    #pragma unroll
    for (int u = 0; u < 8; ++u) {
        int lin = u*128 + tid;
        int key = lin >> 4;
        int d4  = (lin & 15) * 4;
        cp_async16(stK + key*64 + d4, Kb + (size_t)(k0+key)*64 + d4);
        cp_async16(stV + key*64 + d4, Vb + (size_t)(k0+key)*64 + d4);
    }
}

__global__ void __launch_bounds__(128) attn_kernel()
{
    extern __shared__ u32 dsm[];
    u32* Kf = dsm;                       // 32*140 u32
    u32* Vf = Kf + 32*FBLK;
    float* stK = (float*)(Vf + 32*FBLK);
    float* stV = stK + 64*64;

    int tid  = threadIdx.x;
    int warp = tid >> 5;
    int lane = tid & 31;
    int g    = lane >> 2;
    int tg   = lane & 3;

    int bh = blockIdx.y;
    int qt = 31 - (int)blockIdx.x;
    int q0 = qt * 64;

    const float* Qb = g_q + (size_t)bh*SS*DD;
    const float* Kb = g_k + (size_t)bh*SS*DD;
    const float* Vb = g_v + (size_t)bh*SS*DD;

    int r0 = q0 + warp*16 + g;
    int r1 = r0 + 8;

    attn_issue_tile(Kb, Vb, stK, stV, 0, tid);
    cp_commit();

    u32 qa[8][4];
    #pragma unroll
    for (int k = 0; k < 8; ++k) {
        qa[k][0] = cvt_tf32(Qb[(size_t)r0*64 + k*8 + tg]     * 0.125f);
        qa[k][1] = cvt_tf32(Qb[(size_t)r1*64 + k*8 + tg]     * 0.125f);
        qa[k][2] = cvt_tf32(Qb[(size_t)r0*64 + k*8 + tg + 4] * 0.125f);
        qa[k][3] = cvt_tf32(Qb[(size_t)r1*64 + k*8 + tg + 4] * 0.125f);
    }

    float accO[8][4];
    #pragma unroll
    for (int n = 0; n < 8; ++n)
        #pragma unroll
        for (int j = 0; j < 4; ++j) accO[n][j] = 0.f;
    float m0 = -3.0e38f, m1 = -3.0e38f, l0 = 0.f, l1 = 0.f;

    u32* Pw = Kf + warp*(16*PSTRA);      // P aliases Kf region (dead after QK)

    for (int t = 0; t <= qt; ++t) {
        int k0 = t * 64;
        cp_wait<0>();
        __syncthreads();                 // staging ready; Kf/Vf free (prev tile fully consumed)

        // producer: raw fp32 -> tf32 in fragment order (same values, permuted addresses)
        #pragma unroll
        for (int u = 0; u < 8; ++u) {
            int lin = u*128 + tid;
            int key = lin >> 4;
            int d4  = (lin & 15) * 4;
            float4 kv = *(const float4*)(stK + key*64 + d4);
            float4 vv = *(const float4*)(stV + key*64 + d4);
            // K: element (key=n*8+gk, d=k*8+tg+4h)
            {
                int n  = key >> 3, gk = key & 7;
                int k  = d4 >> 3, kp = k >> 1, ko = k & 1, hk = (d4 >> 2) & 1;
                u32* kd = &Kf[(n*4+kp)*FBLK + (gk*4)*4 + ko*2 + hk];
                kd[0]  = cvt_tf32(kv.x);
                kd[4]  = cvt_tf32(kv.y);
                kd[8]  = cvt_tf32(kv.z);
                kd[12] = cvt_tf32(kv.w);
            }
            // V: element (row=key=k2*8+tg+4h, col=d=n2*8+gv)
            {
                int n2 = d4 >> 3;
                int gv = d4 & 7;            // 0 or 4; +j for j=0..3
                int k2 = key >> 3, tv = key & 3, hv = (key >> 2) & 1;
                int k2p = k2 >> 1, k2o = k2 & 1;
                u32* vd = &Vf[(k2p*8+n2)*FBLK + (gv*4 + tv)*4 + k2o*2 + hv];
                vd[0]  = cvt_tf32(vv.x);
                vd[16] = cvt_tf32(vv.y);
                vd[32] = cvt_tf32(vv.z);
                vd[48] = cvt_tf32(vv.w);
            }
        }
        __syncthreads();                 // operands ready; staging free

        if (t < qt) attn_issue_tile(Kb, Vb, stK, stV, k0 + 64, tid);
        cp_commit();

        // S = Q K^T : B-frags via LDS.128 (2 k-steps per load)
        float sfr[8][4];
        #pragma unroll
        for (int n = 0; n < 8; ++n) {
            float c[4] = {0.f, 0.f, 0.f, 0.f};
            #pragma unroll
            for (int kp = 0; kp < 4; ++kp) {
                uint4 bb = *(uint4*)&Kf[(n*4+kp)*FBLK + lane*4];
                mma_tf32(c, qa[2*kp],   bb.x, bb.y);
                mma_tf32(c, qa[2*kp+1], bb.z, bb.w);
            }
            sfr[n][0] = c[0]; sfr[n][1] = c[1]; sfr[n][2] = c[2]; sfr[n][3] = c[3];
        }

        if (t == qt) {
            #pragma unroll
            for (int n = 0; n < 8; ++n) {
                int col = k0 + n*8 + 2*tg;
                if (col     > r0) sfr[n][0] = -1e30f;
                if (col + 1 > r0) sfr[n][1] = -1e30f;
                if (col     > r1) sfr[n][2] = -1e30f;
                if (col + 1 > r1) sfr[n][3] = -1e30f;
            }
        }

        float mx0 = -3.0e38f, mx1 = -3.0e38f;
        #pragma unroll
        for (int n = 0; n < 8; ++n) {
            mx0 = fmaxf(mx0, fmaxf(sfr[n][0], sfr[n][1]));
            mx1 = fmaxf(mx1, fmaxf(sfr[n][2], sfr[n][3]));
        }
        mx0 = fmaxf(mx0, __shfl_xor_sync(0xffffffffu, mx0, 1));
        mx0 = fmaxf(mx0, __shfl_xor_sync(0xffffffffu, mx0, 2));
        mx1 = fmaxf(mx1, __shfl_xor_sync(0xffffffffu, mx1, 1));
        mx1 = fmaxf(mx1, __shfl_xor_sync(0xffffffffu, mx1, 2));
        float nm0 = fmaxf(m0, mx0), nm1 = fmaxf(m1, mx1);
        float cr0 = __expf(m0 - nm0), cr1 = __expf(m1 - nm1);
        m0 = nm0; m1 = nm1;
        l0 *= cr0; l1 *= cr1;
        #pragma unroll
        for (int n = 0; n < 8; ++n) {
            accO[n][0] *= cr0; accO[n][1] *= cr0;
            accO[n][2] *= cr1; accO[n][3] *= cr1;
        }
        float ps0 = 0.f, ps1 = 0.f;
        #pragma unroll
        for (int n = 0; n < 8; ++n) {
            sfr[n][0] = __expf(sfr[n][0] - nm0);
            sfr[n][1] = __expf(sfr[n][1] - nm0);
            sfr[n][2] = __expf(sfr[n][2] - nm1);
            sfr[n][3] = __expf(sfr[n][3] - nm1);
            ps0 += sfr[n][0] + sfr[n][1];
            ps1 += sfr[n][2] + sfr[n][3];
        }
        l0 += ps0; l1 += ps1;

        __syncthreads();                 // all warps done reading Kf (QK)
        #pragma unroll
        for (int n = 0; n < 8; ++n) {
            Pw[g*PSTRA       + n*8 + 2*tg]     = cvt_tf32(sfr[n][0]);
            Pw[g*PSTRA       + n*8 + 2*tg + 1] = cvt_tf32(sfr[n][1]);
            Pw[(g+8)*PSTRA   + n*8 + 2*tg]     = cvt_tf32(sfr[n][2]);
            Pw[(g+8)*PSTRA   + n*8 + 2*tg + 1] = cvt_tf32(sfr[n][3]);
        }
        __syncwarp();

        // O += P V : B-frags via LDS.128 (2 k2-steps per load)
        #pragma unroll
        for (int k2p = 0; k2p < 4; ++k2p) {
            u32 a0[4], a1[4];
            int k2a = 2*k2p, k2b = 2*k2p + 1;
            a0[0] = Pw[g*PSTRA     + k2a*8 + tg];
            a0[1] = Pw[(g+8)*PSTRA + k2a*8 + tg];
            a0[2] = Pw[g*PSTRA     + k2a*8 + tg + 4];
            a0[3] = Pw[(g+8)*PSTRA + k2a*8 + tg + 4];
            a1[0] = Pw[g*PSTRA     + k2b*8 + tg];
            a1[1] = Pw[(g+8)*PSTRA + k2b*8 + tg];
            a1[2] = Pw[g*PSTRA     + k2b*8 + tg + 4];
            a1[3] = Pw[(g+8)*PSTRA + k2b*8 + tg + 4];
            #pragma unroll
            for (int n2 = 0; n2 < 8; ++n2) {
                uint4 bb = *(uint4*)&Vf[(k2p*8+n2)*FBLK + lane*4];
                mma_tf32(accO[n2], a0, bb.x, bb.y);
                mma_tf32(accO[n2], a1, bb.z, bb.w);
            }
        }
    }

    l0 += __shfl_xor_sync(0xffffffffu, l0, 1);
    l0 += __shfl_xor_sync(0xffffffffu, l0, 2);
    l1 += __shfl_xor_sync(0xffffffffu, l1, 1);
    l1 += __shfl_xor_sync(0xffffffffu, l1, 2);
    float inv0 = 1.f / l0, inv1 = 1.f / l1;

    int b = bh >> 4, h = bh & (HH-1);
    float* out0 = g_attn + ((size_t)(b*SS + r0))*EE + h*DD;
    float* out1 = g_attn + ((size_t)(b*SS + r1))*EE + h*DD;
    #pragma unroll
    for (int n2 = 0; n2 < 8; ++n2) {
        float2 v0, v1;
        v0.x = accO[n2][0]*inv0; v0.y = accO[n2][1]*inv0;
        v1.x = accO[n2][2]*inv1; v1.y = accO[n2][3]*inv1;
        *(float2*)(out0 + n2*8 + 2*tg) = v0;
        *(float2*)(out1 + n2*8 + 2*tg) = v1;
    }
}

// ---------------- output projection: tf32 mma + cp.async 2-stage, BK=32 (validated) ----------------
#define PK 32
#define PSTR2 36
#define PROJ_SMEM (2*128*PSTR2*4 + 2*2*128*PK*4)

__device__ __forceinline__ void proj_issue(
    const float* __restrict__ W, float* stA, float* stB,
    int m0, int n0, int i, int tid)
{
    if (i < EE/PK) {
        int k0 = i * PK;
        float* sA = stA + (i & 1) * 128*PK;
        float* sB = stB + (i & 1) * 128*PK;
        #pragma unroll
        for (int it = 0; it < 4; ++it) {
            int idx = it*256 + tid;
            int row = idx >> 3;
            int c4  = (idx & 7) * 4;
            cp_async16(sA + row*PK + c4, g_attn + (size_t)(m0+row)*EE + k0 + c4);
            cp_async16(sB + row*PK + c4, W + (size_t)(n0+row)*EE + k0 + c4);
        }
    }
    cp_commit();
}

__global__ __launch_bounds__(256) void proj_kernel(
    const float* __restrict__ W, const float* __restrict__ bias, float* __restrict__ out)
{
    extern __shared__ u32 dsm[];
    u32* As = dsm;
    u32* Bs = dsm + 128*PSTR2;
    float* stA = (float*)(dsm + 2*128*PSTR2);
    float* stB = stA + 2*128*PK;

    int tid  = threadIdx.x;
    int warp = tid >> 5;
    int lane = tid & 31;
    int g    = lane >> 2;
    int tg   = lane & 3;
    int wm0  = (warp >> 1) * 32;
    int wn0  = (warp & 1) * 64;
    int m0   = blockIdx.y * 128;
    int n0   = blockIdx.x * 128;

    float acc[2][8][4];
    #pragma unroll
    for (int mf = 0; mf < 2; ++mf)
        #pragma unroll
        for (int nf = 0; nf < 8; ++nf)
            #pragma unroll
            for (int j = 0; j < 4; ++j) acc[mf][nf][j] = 0.f;

    proj_issue(W, stA, stB, m0, n0, 0, tid);
    proj_issue(W, stA, stB, m0, n0, 1, tid);

    for (int i = 0; i < EE/PK; ++i) {
        cp_wait<1>();
        __syncthreads();

        float* sA = stA + (i & 1) * 128*PK;
        float* sB = stB + (i & 1) * 128*PK;
        #pragma unroll
        for (int it = 0; it < 4; ++it) {
            int idx = it*256 + tid;
            int row = idx >> 3;
            int c4  = (idx & 7) * 4;
            float4 a = *(const float4*)(sA + row*PK + c4);
            uint4 ha;
            ha.x = cvt_tf32(a.x); ha.y = cvt_tf32(a.y); ha.z = cvt_tf32(a.z); ha.w = cvt_tf32(a.w);
            *(uint4*)&As[row*PSTR2 + c4] = ha;
            float4 b = *(const float4*)(sB + row*PK + c4);
            uint4 hb;
            hb.x = cvt_tf32(b.x); hb.y = cvt_tf32(b.y); hb.z = cvt_tf32(b.z); hb.w = cvt_tf32(b.w);
            *(uint4*)&Bs[row*PSTR2 + c4] = hb;
        }
        __syncthreads();

        proj_issue(W, stA, stB, m0, n0, i + 2, tid);

        #pragma unroll
        for (int ks = 0; ks < 4; ++ks) {
            int kk = ks * 8;
            u32 a[2][4];
            #pragma unroll
            for (int mf = 0; mf < 2; ++mf) {
                int mr = wm0 + mf*16;
                a[mf][0] = As[(mr+g)*PSTR2   + kk + tg];
                a[mf][1] = As[(mr+g+8)*PSTR2 + kk + tg];
                a[mf][2] = As[(mr+g)*PSTR2   + kk + tg + 4];
                a[mf][3] = As[(mr+g+8)*PSTR2 + kk + tg + 4];
            }
            #pragma unroll
            for (int nf = 0; nf < 8; ++nf) {
                u32 b0 = Bs[(wn0 + nf*8 + g)*PSTR2 + kk + tg];
                u32 b1 = Bs[(wn0 + nf*8 + g)*PSTR2 + kk + tg + 4];
                #pragma unroll
                for (int mf = 0; mf < 2; ++mf)
                    mma_tf32(acc[mf][nf], a[mf], b0, b1);
            }
        }
    }

    #pragma unroll
    for (int mf = 0; mf < 2; ++mf) {
        int ra = m0 + wm0 + mf*16 + g;
        int rb = ra + 8;
        #pragma unroll
        for (int nf = 0; nf < 8; ++nf) {
            int gc = n0 + wn0 + nf*8 + 2*tg;
            float b0 = bias[gc], b1 = bias[gc+1];
            float2 t0, t1;
            t0.x = acc[mf][nf][0] + b0; t0.y = acc[mf][nf][1] + b1;
            t1.x = acc[mf][nf][2] + b0; t1.y = acc[mf][nf][3] + b1;
            *(float2*)(out + (size_t)ra*EE + gc) = t0;
            *(float2*)(out + (size_t)rb*EE + gc) = t1;
        }
    }
}

// ---------------- launch ----------------
extern "C" void kernel_launch(void* const* d_in, const int* in_sizes, int n_in,
                              void* d_out, int out_size) {
    const float* x  = (const float*)d_in[0];
    const float* Wq = (const float*)d_in[1];
    const float* Bq = (const float*)d_in[2];
    const float* Wk = (const float*)d_in[3];
    const float* Bk = (const float*)d_in[4];
    const float* Wv = (const float*)d_in[5];
    const float* Bv = (const float*)d_in[6];
    const float* Pw = (const float*)d_in[7];
    const float* Pb = (const float*)d_in[8];
    float* out = (float*)d_out;

    cudaFuncSetAttribute(attn_kernel, cudaFuncAttributeMaxDynamicSharedMemorySize, ATTN_SMEM);
    cudaFuncSetAttribute(proj_kernel, cudaFuncAttributeMaxDynamicSharedMemorySize, PROJ_SMEM);

    qkv_kernel<<<1024, 256>>>(x, Wq, Bq, Wk, Bk, Wv, Bv);
    attn_kernel<<<dim3(32, 32), 128, ATTN_SMEM>>>();
    proj_kernel<<<dim3(8, 32), 256, PROJ_SMEM>>>(Pw, Pb, out);
}